// round 10
// baseline (speedup 1.0000x reference)
#include <cuda_runtime.h>
#include <cuda_fp16.h>

// y = FWHT(G * Perm(FWHT(x * B))), orthonormal, L = 16384, fused one-pass.
//
// Persistent CTAs (grid = 2*148), each processes ~14 rows. fp16 SMEM data,
// fp32 packed f32x2 register math. 512 thr/CTA, 2 CTA/SM (96KB smem each):
//   smem = [A: 8192 half2][B: 8192 half2][Pisw: 8192 u32, THREAD-ACCESS order]
// Bit plan per FWHT (word space q = n>>1):
//   P1: {n0 scalar, n1,n11,n12,n13 packed}; lanes = n2..n10 (coalesced f4)
//   P2: word bits {q1,q2,q7,q8} = {n2,n3,n8,n9} (in-place)
//   P3: word bits {q3..q6} = {n4..n7}; n10 via __shfl_xor(word,16)
// Swizzle swq (GF(2)-linear) keeps all structured passes conflict-free.
// Row flow: P1->A | P2 in A | P3 ld A, z=y1*Gp st B | gather B (addrs from
// smem Pisw) -> P3' st A (no barrier: A idle since pass-5 barrier) | P2' in A
// | P1' -> gmem.
// R9 FIX: prologue stores Pisw pairs in thread-access order:
//   sPi[(w<<9)+t] = gp32[p3q | (w<<3)]   (R8 wrongly cached identity order,
//   so gathers used other threads' indices -> rel_err sqrt(2)).
// Prep: Bbits sign table; Gph[Pi[n]] = half(G[n]/16384); Pisw[n] = swizzled
// half-address of Pi[n] (u16).

#define L_N        16384
#define NQ         (L_N / 2)            // 8192 words per buffer
#define NT         512
#define SMEM_WORDS (3 * NQ)             // A + B + Pisw
#define SMEM_BYTES (SMEM_WORDS * 4)     // 98304

typedef unsigned long long ull;

__device__ __align__(16) unsigned       g_Bbits[L_N / 32];
__device__ __align__(16) unsigned short g_Pisw[L_N];
__device__ __align__(16) __half         g_Gph[L_N];

__device__ __forceinline__ int swq(int q) {
    int f = (((q >> 5) & 1) << 1) ^ (((q >> 9) & 1) << 2) ^ (((q >> 7) & 1) << 3)
          ^ ((((q >> 2) ^ (q >> 8)) & 1) << 4);
    return q ^ f;
}

// ---- packed f32x2 helpers ----
__device__ __forceinline__ ull padd(ull a, ull b) {
    ull r; asm("add.rn.f32x2 %0, %1, %2;" : "=l"(r) : "l"(a), "l"(b)); return r;
}
__device__ __forceinline__ ull pmul(ull a, ull b) {
    ull r; asm("mul.rn.f32x2 %0, %1, %2;" : "=l"(r) : "l"(a), "l"(b)); return r;
}
__device__ __forceinline__ ull psub(ull a, ull b) {   // a - b
    const ull N1 = 0xBF800000BF800000ULL;
    ull r; asm("fma.rn.f32x2 %0, %1, %2, %3;" : "=l"(r) : "l"(b), "l"(N1), "l"(a));
    return r;
}
__device__ __forceinline__ ull pk2(float lo, float hi) {
    ull r; asm("mov.b64 %0, {%1, %2};" : "=l"(r) : "f"(lo), "f"(hi)); return r;
}
__device__ __forceinline__ float2 upk2(ull v) {
    float2 f; asm("mov.b64 {%0, %1}, %2;" : "=f"(f.x), "=f"(f.y) : "l"(v)); return f;
}
__device__ __forceinline__ ull h2_to_p(unsigned u) {
    __half2 h = *reinterpret_cast<__half2*>(&u);
    float2 f = __half22float2(h);
    return pk2(f.x, f.y);
}
__device__ __forceinline__ unsigned p_to_h2(ull v) {
    float2 f = upk2(v);
    __half2 h = __float22half2_rn(f);
    return *reinterpret_cast<unsigned*>(&h);
}

__device__ __forceinline__ void bflyp(ull &A, ull &B) {
    ull s_ = padd(A, B);
    ull d_ = psub(A, B);
    A = s_; B = d_;
}

__device__ __forceinline__ void fwht16p(ull W[16]) {
#pragma unroll
    for (int m = 1; m < 16; m <<= 1) {
#pragma unroll
        for (int i = 0; i < 16; i++) {
            if ((i & m) == 0) bflyp(W[i], W[i | m]);
        }
    }
}

// swizzle deltas for phase-local word bits (constants under full unroll)
__device__ __forceinline__ int d2c(int w) {   // wbits {q1,q2,q7,q8}
    int wb = ((w & 1) << 1) | (((w >> 1) & 1) << 2) | (((w >> 2) & 1) << 7)
           | (((w >> 3) & 1) << 8);
    int f = ((((w >> 1) ^ (w >> 3)) & 1) << 4) ^ (((w >> 2) & 1) << 3);
    return wb ^ f;
}
__device__ __forceinline__ int d3c(int w) {   // wbits {q3..q6}; q5 -> b1
    return (w << 3) ^ (((w >> 2) & 1) << 1);
}

__global__ void prep_kernel(const float* __restrict__ Gv,
                            const int* __restrict__ Pi,
                            const float* __restrict__ Bv) {
    int n = blockIdx.x * blockDim.x + threadIdx.x;   // 16384 threads
    int p = Pi[n];
    g_Pisw[n] = (unsigned short)((swq(p >> 1) << 1) | (p & 1));
    g_Gph[p]  = __float2half(Gv[n] * (1.0f / 16384.0f));
    unsigned sb  = __float_as_uint(Bv[n]) >> 31;
    unsigned bal = __ballot_sync(0xffffffffu, sb);
    if ((n & 31) == 0) g_Bbits[n >> 5] = bal;
}

__global__ __launch_bounds__(NT, 2)
void fwht_fused_kernel(const float* __restrict__ x,
                       float* __restrict__ out, int rows) {
    extern __shared__ unsigned s32[];
    unsigned* const sA  = s32;                 // data buffer A
    unsigned* const sB  = s32 + NQ;            // z buffer (pass5 / gather)
    unsigned* const sPi = s32 + 2 * NQ;        // Pisw pairs, thread-access order
    const int t = threadIdx.x;

    ull W[16];

    // phase base words (swizzled once; phase-local bits XORed per access)
    const int base1 = swq(t << 1);
    const int p2q = (t & 1) | (((t >> 1) & 7) << 3) | (((t >> 4) & 1) << 9)
                  | (((t >> 5) & 1) << 6) | (((t >> 6) & 7) << 10);
    const int base2 = swq(p2q);
    const int p3q = (t & 7) | (((t >> 3) & 1) << 7) | (((t >> 4) & 1) << 9)
                  | (((t >> 5) & 1) << 8) | (((t >> 6) & 7) << 10);
    const int base3 = swq(p3q);

    // ---- prologue: cache Pisw pairs in smem, permuted to THREAD-ACCESS order
    // (slot (w<<9)+t holds the pair for word p3q|(w<<3); writer == reader) ----
    {
        const unsigned* __restrict__ gp32 =
            reinterpret_cast<const unsigned*>(g_Pisw);
#pragma unroll
        for (int w = 0; w < 16; w++)
            sPi[(w << 9) + t] = gp32[p3q | (w << 3)];
    }
    __syncthreads();

    for (int row = blockIdx.x; row < rows; row += gridDim.x) {

        // ===== FWHT#1 P1: scalar n0 stage at load, packed {n1,n11,n12,n13} =====
        {
            const float4* __restrict__ x4 =
                reinterpret_cast<const float4*>(x + (size_t)row * L_N);
#pragma unroll
            for (int k = 0; k < 8; k++) {
                float4 xv = x4[(k << 9) + t];
                unsigned u = g_Bbits[(k << 6) + (t >> 3)] >> ((t & 7) << 2);
                float a = __uint_as_float(__float_as_uint(xv.x) ^ ((u & 1u) << 31));
                float b = __uint_as_float(__float_as_uint(xv.y) ^ ((u & 2u) << 30));
                float c = __uint_as_float(__float_as_uint(xv.z) ^ ((u & 4u) << 29));
                float d = __uint_as_float(__float_as_uint(xv.w) ^ ((u & 8u) << 28));
                W[2 * k]     = pk2(a + b, a - b);
                W[2 * k + 1] = pk2(c + d, c - d);
            }
        }
        fwht16p(W);
#pragma unroll
        for (int k = 0; k < 8; k++) {
            uint2 v;
            v.x = p_to_h2(W[2 * k]);
            v.y = p_to_h2(W[2 * k + 1]);
            *reinterpret_cast<uint2*>(&sA[base1 ^ (k << 10)]) = v;
        }
        __syncthreads();

        // ===== FWHT#1 P2: word bits {q1,q2,q7,q8} (in-place in A) =====
#pragma unroll
        for (int w = 0; w < 16; w++) W[w] = h2_to_p(sA[base2 ^ d2c(w)]);
        fwht16p(W);
#pragma unroll
        for (int w = 0; w < 16; w++) sA[base2 ^ d2c(w)] = p_to_h2(W[w]);
        __syncthreads();

        // ===== FWHT#1 P3: shfl butterfly (n10) + word bits {q3..q6} =====
#pragma unroll
        for (int w = 0; w < 16; w++) {
            unsigned pw = sA[base3 ^ d3c(w)];
            unsigned qw = __shfl_xor_sync(0xffffffffu, pw, 16);
            ull A = h2_to_p(pw), Bp = h2_to_p(qw);
            W[w] = (t & 16) ? psub(Bp, A) : padd(A, Bp);
        }
        fwht16p(W);

        // ===== pass 5: z = y1 * Gp (G + 1/16384 folded, fp16), store to B =====
#pragma unroll
        for (int w = 0; w < 16; w++) {
            unsigned gph = *reinterpret_cast<const unsigned*>(
                &g_Gph[(p3q | (w << 3)) << 1]);
            sB[base3 ^ d3c(w)] = p_to_h2(pmul(W[w], h2_to_p(gph)));
        }
        __syncthreads();

        // ===== gather from B (addresses from smem Pisw) + shfl bfly (n10) =====
        {
            const unsigned short* __restrict__ shB =
                reinterpret_cast<const unsigned short*>(sB);
#pragma unroll
            for (int w = 0; w < 16; w++) {
                unsigned pp = sPi[(w << 9) + t];
                unsigned h0 = shB[pp & 0xffffu];
                unsigned h1 = shB[pp >> 16];
                unsigned pw = __byte_perm(h0, h1, 0x5410);
                unsigned qw = __shfl_xor_sync(0xffffffffu, pw, 16);
                ull A = h2_to_p(pw), Bp = h2_to_p(qw);
                W[w] = (t & 16) ? psub(Bp, A) : padd(A, Bp);
            }
        }
        // no barrier: P3' stores go to A, whose last reads finished before
        // the pass-5 barrier; gather reads only B + sPi.

        // ===== FWHT#2 P3: word bits {q3..q6}, store to A =====
        fwht16p(W);
#pragma unroll
        for (int w = 0; w < 16; w++) sA[base3 ^ d3c(w)] = p_to_h2(W[w]);
        __syncthreads();

        // ===== FWHT#2 P2: word bits {q1,q2,q7,q8} (in-place in A) =====
#pragma unroll
        for (int w = 0; w < 16; w++) W[w] = h2_to_p(sA[base2 ^ d2c(w)]);
        fwht16p(W);
#pragma unroll
        for (int w = 0; w < 16; w++) sA[base2 ^ d2c(w)] = p_to_h2(W[w]);
        __syncthreads();

        // ===== FWHT#2 P1: packed {n1,n11,n12,n13}, scalar n0, f4 store =====
#pragma unroll
        for (int k = 0; k < 8; k++) {
            uint2 v = *reinterpret_cast<const uint2*>(&sA[base1 ^ (k << 10)]);
            W[2 * k]     = h2_to_p(v.x);
            W[2 * k + 1] = h2_to_p(v.y);
        }
        fwht16p(W);
        {
            float4* __restrict__ o4 =
                reinterpret_cast<float4*>(out + (size_t)row * L_N);
#pragma unroll
            for (int k = 0; k < 8; k++) {
                float2 f0 = upk2(W[2 * k]);
                float2 f1 = upk2(W[2 * k + 1]);
                o4[(k << 9) + t] = make_float4(f0.x + f0.y, f0.x - f0.y,
                                               f1.x + f1.y, f1.x - f1.y);
            }
        }
        __syncthreads();   // A reads done before next row's P1 store
    }
}

extern "C" void kernel_launch(void* const* d_in, const int* in_sizes, int n_in,
                              void* d_out, int out_size) {
    const float* x  = (const float*)d_in[0];
    const float* B  = (const float*)d_in[1];
    const float* G  = (const float*)d_in[2];
    const int*   Pi = (const int*)d_in[3];
    float* out = (float*)d_out;

    int rows = in_sizes[0] / L_N;
    int grid = rows < 296 ? rows : 296;   // 2 CTAs per SM, persistent

    cudaFuncSetAttribute(fwht_fused_kernel,
                         cudaFuncAttributeMaxDynamicSharedMemorySize, SMEM_BYTES);

    prep_kernel<<<L_N / 256, 256>>>(G, Pi, B);
    fwht_fused_kernel<<<grid, NT, SMEM_BYTES>>>(x, out, rows);
}

// round 11
// speedup vs baseline: 1.1580x; 1.1580x over previous
#include <cuda_runtime.h>
#include <cuda_fp16.h>

// y = FWHT(G * Perm(FWHT(x * B))), orthonormal, L = 16384, fused one-pass.
//
// Grid = 4096 (one row/CTA, natural wave balance), 512 thr/CTA, 2 CTA/SM.
// fp16 SMEM data in TWO buffers (A,B; 64KB total), fp32 packed f32x2 math.
// Bit plan per FWHT (word space q = n>>1):
//   P1: {n0 scalar, n1,n11,n12,n13 packed}; lanes = n2..n10 (coalesced f4)
//   P2: word bits {q1,q2,q7,q8} = {n2,n3,n8,n9} (in-place in A)
//   P3: word bits {q3..q6} = {n4..n7}; n10 via __shfl_xor(word,16)
// Swizzle swq (GF(2)-linear) keeps all structured passes conflict-free.
// Row flow: P1->A | P2 in A | P3 ld A, z=y1*Gp st B | gather B (u16 global
// Pisw addrs) -> P3' st A (NO barrier: A idle since pass-5 barrier) | P2' in A
// | P1' -> gmem.  5 barriers/row (was 6).
// Prep: Bbits sign table; Gph[Pi[n]] = half(G[n]/16384); Pisw[n] = swizzled
// half-address of Pi[n] (u16).

#define L_N        16384
#define NQ         (L_N / 2)            // 8192 words per buffer
#define NT         512
#define SMEM_BYTES (2 * NQ * 4)         // 65536 (A + B)

typedef unsigned long long ull;

__device__ __align__(16) unsigned       g_Bbits[L_N / 32];
__device__ __align__(16) unsigned short g_Pisw[L_N];
__device__ __align__(16) __half         g_Gph[L_N];

__device__ __forceinline__ int swq(int q) {
    int f = (((q >> 5) & 1) << 1) ^ (((q >> 9) & 1) << 2) ^ (((q >> 7) & 1) << 3)
          ^ ((((q >> 2) ^ (q >> 8)) & 1) << 4);
    return q ^ f;
}

// ---- packed f32x2 helpers ----
__device__ __forceinline__ ull padd(ull a, ull b) {
    ull r; asm("add.rn.f32x2 %0, %1, %2;" : "=l"(r) : "l"(a), "l"(b)); return r;
}
__device__ __forceinline__ ull pmul(ull a, ull b) {
    ull r; asm("mul.rn.f32x2 %0, %1, %2;" : "=l"(r) : "l"(a), "l"(b)); return r;
}
__device__ __forceinline__ ull psub(ull a, ull b) {   // a - b
    const ull N1 = 0xBF800000BF800000ULL;
    ull r; asm("fma.rn.f32x2 %0, %1, %2, %3;" : "=l"(r) : "l"(b), "l"(N1), "l"(a));
    return r;
}
__device__ __forceinline__ ull pk2(float lo, float hi) {
    ull r; asm("mov.b64 %0, {%1, %2};" : "=l"(r) : "f"(lo), "f"(hi)); return r;
}
__device__ __forceinline__ float2 upk2(ull v) {
    float2 f; asm("mov.b64 {%0, %1}, %2;" : "=f"(f.x), "=f"(f.y) : "l"(v)); return f;
}
__device__ __forceinline__ ull h2_to_p(unsigned u) {
    __half2 h = *reinterpret_cast<__half2*>(&u);
    float2 f = __half22float2(h);
    return pk2(f.x, f.y);
}
__device__ __forceinline__ unsigned p_to_h2(ull v) {
    float2 f = upk2(v);
    __half2 h = __float22half2_rn(f);
    return *reinterpret_cast<unsigned*>(&h);
}

__device__ __forceinline__ void bflyp(ull &A, ull &B) {
    ull s_ = padd(A, B);
    ull d_ = psub(A, B);
    A = s_; B = d_;
}

__device__ __forceinline__ void fwht16p(ull W[16]) {
#pragma unroll
    for (int m = 1; m < 16; m <<= 1) {
#pragma unroll
        for (int i = 0; i < 16; i++) {
            if ((i & m) == 0) bflyp(W[i], W[i | m]);
        }
    }
}

// swizzle deltas for phase-local word bits (constants under full unroll)
__device__ __forceinline__ int d2c(int w) {   // wbits {q1,q2,q7,q8}
    int wb = ((w & 1) << 1) | (((w >> 1) & 1) << 2) | (((w >> 2) & 1) << 7)
           | (((w >> 3) & 1) << 8);
    int f = ((((w >> 1) ^ (w >> 3)) & 1) << 4) ^ (((w >> 2) & 1) << 3);
    return wb ^ f;
}
__device__ __forceinline__ int d3c(int w) {   // wbits {q3..q6}; q5 -> b1
    return (w << 3) ^ (((w >> 2) & 1) << 1);
}

__global__ void prep_kernel(const float* __restrict__ Gv,
                            const int* __restrict__ Pi,
                            const float* __restrict__ Bv) {
    int n = blockIdx.x * blockDim.x + threadIdx.x;   // 16384 threads
    int p = Pi[n];
    g_Pisw[n] = (unsigned short)((swq(p >> 1) << 1) | (p & 1));
    g_Gph[p]  = __float2half(Gv[n] * (1.0f / 16384.0f));
    unsigned sb  = __float_as_uint(Bv[n]) >> 31;
    unsigned bal = __ballot_sync(0xffffffffu, sb);
    if ((n & 31) == 0) g_Bbits[n >> 5] = bal;
}

__global__ __launch_bounds__(NT, 2)
void fwht_fused_kernel(const float* __restrict__ x,
                       float* __restrict__ out) {
    extern __shared__ unsigned s32[];
    unsigned* const sA = s32;          // data buffer A
    unsigned* const sB = s32 + NQ;     // z buffer (pass5 / gather)
    const int t = threadIdx.x;
    const size_t row = blockIdx.x;

    ull W[16];

    // phase base words (swizzled once; phase-local bits XORed per access)
    const int base1 = swq(t << 1);
    const int p2q = (t & 1) | (((t >> 1) & 7) << 3) | (((t >> 4) & 1) << 9)
                  | (((t >> 5) & 1) << 6) | (((t >> 6) & 7) << 10);
    const int base2 = swq(p2q);
    const int p3q = (t & 7) | (((t >> 3) & 1) << 7) | (((t >> 4) & 1) << 9)
                  | (((t >> 5) & 1) << 8) | (((t >> 6) & 7) << 10);
    const int base3 = swq(p3q);

    // ===== FWHT#1 P1: scalar n0 stage at load, packed {n1,n11,n12,n13} =====
    {
        const float4* __restrict__ x4 =
            reinterpret_cast<const float4*>(x + row * L_N);
#pragma unroll
        for (int k = 0; k < 8; k++) {
            float4 xv = x4[(k << 9) + t];
            unsigned u = g_Bbits[(k << 6) + (t >> 3)] >> ((t & 7) << 2);
            float a = __uint_as_float(__float_as_uint(xv.x) ^ ((u & 1u) << 31));
            float b = __uint_as_float(__float_as_uint(xv.y) ^ ((u & 2u) << 30));
            float c = __uint_as_float(__float_as_uint(xv.z) ^ ((u & 4u) << 29));
            float d = __uint_as_float(__float_as_uint(xv.w) ^ ((u & 8u) << 28));
            W[2 * k]     = pk2(a + b, a - b);
            W[2 * k + 1] = pk2(c + d, c - d);
        }
    }
    fwht16p(W);
#pragma unroll
    for (int k = 0; k < 8; k++) {
        uint2 v;
        v.x = p_to_h2(W[2 * k]);
        v.y = p_to_h2(W[2 * k + 1]);
        *reinterpret_cast<uint2*>(&sA[base1 ^ (k << 10)]) = v;
    }
    __syncthreads();

    // ===== FWHT#1 P2: word bits {q1,q2,q7,q8} (in-place in A) =====
#pragma unroll
    for (int w = 0; w < 16; w++) W[w] = h2_to_p(sA[base2 ^ d2c(w)]);
    fwht16p(W);
#pragma unroll
    for (int w = 0; w < 16; w++) sA[base2 ^ d2c(w)] = p_to_h2(W[w]);
    __syncthreads();

    // ===== FWHT#1 P3: shfl butterfly (n10) + word bits {q3..q6} =====
#pragma unroll
    for (int w = 0; w < 16; w++) {
        unsigned pw = sA[base3 ^ d3c(w)];
        unsigned qw = __shfl_xor_sync(0xffffffffu, pw, 16);
        ull A = h2_to_p(pw), Bp = h2_to_p(qw);
        W[w] = (t & 16) ? psub(Bp, A) : padd(A, Bp);
    }
    fwht16p(W);

    // ===== pass 5: z = y1 * Gp (G + 1/16384 folded, fp16), store to B =====
#pragma unroll
    for (int w = 0; w < 16; w++) {
        unsigned gph = *reinterpret_cast<const unsigned*>(
            &g_Gph[(p3q | (w << 3)) << 1]);
        sB[base3 ^ d3c(w)] = p_to_h2(pmul(W[w], h2_to_p(gph)));
    }
    __syncthreads();

    // ===== gather from B (u16 global Pisw addrs) + shfl bfly (n10) =====
    {
        const unsigned short* __restrict__ shB =
            reinterpret_cast<const unsigned short*>(sB);
#pragma unroll
        for (int w = 0; w < 16; w++) {
            int n = (p3q | (w << 3)) << 1;
            unsigned pp = *reinterpret_cast<const unsigned*>(&g_Pisw[n]);
            unsigned h0 = shB[pp & 0xffffu];
            unsigned h1 = shB[pp >> 16];
            unsigned pw = __byte_perm(h0, h1, 0x5410);
            unsigned qw = __shfl_xor_sync(0xffffffffu, pw, 16);
            ull A = h2_to_p(pw), Bp = h2_to_p(qw);
            W[w] = (t & 16) ? psub(Bp, A) : padd(A, Bp);
        }
    }
    // NO barrier here: P3' stores go to A, whose last reads (P3 loads)
    // completed before the pass-5 barrier; gather touched only B.

    // ===== FWHT#2 P3: word bits {q3..q6}, store to A =====
    fwht16p(W);
#pragma unroll
    for (int w = 0; w < 16; w++) sA[base3 ^ d3c(w)] = p_to_h2(W[w]);
    __syncthreads();

    // ===== FWHT#2 P2: word bits {q1,q2,q7,q8} (in-place in A) =====
#pragma unroll
    for (int w = 0; w < 16; w++) W[w] = h2_to_p(sA[base2 ^ d2c(w)]);
    fwht16p(W);
#pragma unroll
    for (int w = 0; w < 16; w++) sA[base2 ^ d2c(w)] = p_to_h2(W[w]);
    __syncthreads();

    // ===== FWHT#2 P1: packed {n1,n11,n12,n13}, scalar n0, f4 store =====
#pragma unroll
    for (int k = 0; k < 8; k++) {
        uint2 v = *reinterpret_cast<const uint2*>(&sA[base1 ^ (k << 10)]);
        W[2 * k]     = h2_to_p(v.x);
        W[2 * k + 1] = h2_to_p(v.y);
    }
    fwht16p(W);
    {
        float4* __restrict__ o4 = reinterpret_cast<float4*>(out + row * L_N);
#pragma unroll
        for (int k = 0; k < 8; k++) {
            float2 f0 = upk2(W[2 * k]);
            float2 f1 = upk2(W[2 * k + 1]);
            o4[(k << 9) + t] = make_float4(f0.x + f0.y, f0.x - f0.y,
                                           f1.x + f1.y, f1.x - f1.y);
        }
    }
}

extern "C" void kernel_launch(void* const* d_in, const int* in_sizes, int n_in,
                              void* d_out, int out_size) {
    const float* x  = (const float*)d_in[0];
    const float* B  = (const float*)d_in[1];
    const float* G  = (const float*)d_in[2];
    const int*   Pi = (const int*)d_in[3];
    float* out = (float*)d_out;

    int rows = in_sizes[0] / L_N;

    cudaFuncSetAttribute(fwht_fused_kernel,
                         cudaFuncAttributeMaxDynamicSharedMemorySize, SMEM_BYTES);

    prep_kernel<<<L_N / 256, 256>>>(G, Pi, B);
    fwht_fused_kernel<<<rows, NT, SMEM_BYTES>>>(x, out);
}